// round 1
// baseline (speedup 1.0000x reference)
#include <cuda_runtime.h>

// ---------------------------------------------------------------------------
// Problem constants (shapes fixed by reference): N=50000, E=800000, F=256
// ---------------------------------------------------------------------------
#define NMAX 50176   // 50000 rounded up to multiple of 128

// Scratch (device globals; allocation-free kernel_launch)
__device__ float g_dinv[NMAX];                     // deg, then deg^{-1/2}
__device__ float g_h1  [(size_t)NMAX * 128];       // x@W1, later relu(agg1+b1)
__device__ float g_agg1[(size_t)NMAX * 128];
__device__ float g_h2  [(size_t)NMAX * 12];        // out1@W2, later relu(agg2+b2)
__device__ float g_agg2[(size_t)NMAX * 12];
__device__ float g_m1  [(size_t)NMAX * 512];       // relu(out2@L1+lb1)
__device__ float g_m2  [(size_t)NMAX * 512];       // relu(m1@L2+lb2)

// ---------------------------------------------------------------------------
// Degree / normalization
// ---------------------------------------------------------------------------
__global__ void k_deg_init(int n) {
    int i = blockIdx.x * blockDim.x + threadIdx.x;
    if (i < n) g_dinv[i] = 1.0f;   // self-loop contributes 1
}

__global__ void k_deg_edges(const int* __restrict__ col, int E) {
    int e = blockIdx.x * blockDim.x + threadIdx.x;
    if (e < E) atomicAdd(&g_dinv[col[e]], 1.0f);
}

__global__ void k_deg_rsqrt(int n) {
    int i = blockIdx.x * blockDim.x + threadIdx.x;
    if (i < n) g_dinv[i] = rsqrtf(g_dinv[i]);
}

// ---------------------------------------------------------------------------
// Tiled fp32 SGEMM: C[M,N] = A[M,K] @ B[K,N], optional fused bias+ReLU.
// 128x128 block tile, K-tile 8, 256 threads, 8x8 per thread (quadrant map).
// Requires: K % 8 == 0, N % 128 == 0. M-edge guarded.
// ---------------------------------------------------------------------------
template <bool EPI>
__global__ void __launch_bounds__(256) k_sgemm(
    const float* __restrict__ A, const float* __restrict__ B,
    const float* __restrict__ bias, float* __restrict__ C,
    int M, int N, int K)
{
    __shared__ float As[8][128];
    __shared__ float Bs[8][128];

    const int tid = threadIdx.x;
    const int bm  = blockIdx.x * 128;
    const int bn  = blockIdx.y * 128;
    const int tx  = tid & 15;
    const int ty  = tid >> 4;

    // A tile loaders: 128 rows x 8 cols, float4 per thread
    const int arow = tid >> 1;
    const int acol = (tid & 1) * 4;
    const bool avalid = (bm + arow) < M;
    const float* Aptr = A + (size_t)(bm + arow) * K + acol;

    // B tile loaders: 8 rows x 128 cols, float4 per thread
    const int brow = tid >> 5;
    const int bcol = (tid & 31) * 4;
    const float* Bptr = B + (size_t)brow * N + bn + bcol;

    float acc[8][8];
#pragma unroll
    for (int i = 0; i < 8; i++)
#pragma unroll
        for (int j = 0; j < 8; j++) acc[i][j] = 0.f;

    for (int k0 = 0; k0 < K; k0 += 8) {
        float4 av = avalid ? *(const float4*)(Aptr + k0)
                           : make_float4(0.f, 0.f, 0.f, 0.f);
        float4 bv = *(const float4*)(Bptr + (size_t)k0 * N);

        As[acol + 0][arow] = av.x;
        As[acol + 1][arow] = av.y;
        As[acol + 2][arow] = av.z;
        As[acol + 3][arow] = av.w;
        *(float4*)&Bs[brow][bcol] = bv;
        __syncthreads();

#pragma unroll
        for (int kk = 0; kk < 8; kk++) {
            float4 a0 = *(const float4*)&As[kk][ty * 4];
            float4 a1 = *(const float4*)&As[kk][64 + ty * 4];
            float4 b0 = *(const float4*)&Bs[kk][tx * 4];
            float4 b1 = *(const float4*)&Bs[kk][64 + tx * 4];
            float ra[8] = {a0.x, a0.y, a0.z, a0.w, a1.x, a1.y, a1.z, a1.w};
            float rb[8] = {b0.x, b0.y, b0.z, b0.w, b1.x, b1.y, b1.z, b1.w};
#pragma unroll
            for (int i = 0; i < 8; i++)
#pragma unroll
                for (int j = 0; j < 8; j++)
                    acc[i][j] += ra[i] * rb[j];
        }
        __syncthreads();
    }

#pragma unroll
    for (int i = 0; i < 8; i++) {
        int m = bm + ((i < 4) ? (ty * 4 + i) : (64 + ty * 4 + i - 4));
        if (m >= M) continue;
#pragma unroll
        for (int h = 0; h < 2; h++) {
            int n = bn + h * 64 + tx * 4;
            float4 v;
            v.x = acc[i][h * 4 + 0];
            v.y = acc[i][h * 4 + 1];
            v.z = acc[i][h * 4 + 2];
            v.w = acc[i][h * 4 + 3];
            if (EPI) {
                v.x = fmaxf(v.x + bias[n + 0], 0.f);
                v.y = fmaxf(v.y + bias[n + 1], 0.f);
                v.z = fmaxf(v.z + bias[n + 2], 0.f);
                v.w = fmaxf(v.w + bias[n + 3], 0.f);
            }
            *(float4*)(C + (size_t)m * N + n) = v;
        }
    }
}

// ---------------------------------------------------------------------------
// GCN message passing, layer 1 (128-dim features)
// ---------------------------------------------------------------------------
// Self-loop term doubles as zero-init: agg1 = h1 * dinv^2
__global__ void k_selfloop128(int n) {
    int idx = blockIdx.x * blockDim.x + threadIdx.x;  // over n*32 float4s
    if (idx >= n * 32) return;
    int node = idx >> 5;
    float d = g_dinv[node];
    d = d * d;
    float4 v = ((const float4*)g_h1)[idx];
    v.x *= d; v.y *= d; v.z *= d; v.w *= d;
    ((float4*)g_agg1)[idx] = v;
}

// One warp per edge: gather h1[row] (float4/lane), scale, vector-RED into agg1[col]
__global__ void k_edge_scatter128(const int* __restrict__ row,
                                  const int* __restrict__ col, int E) {
    int gt = blockIdx.x * blockDim.x + threadIdx.x;
    int e = gt >> 5;
    if (e >= E) return;
    int lane = gt & 31;
    int r = row[e], c = col[e];
    float nrm = g_dinv[r] * g_dinv[c];
    float4 v = ((const float4*)(g_h1 + (size_t)r * 128))[lane];
    v.x *= nrm; v.y *= nrm; v.z *= nrm; v.w *= nrm;
    float* dst = g_agg1 + (size_t)c * 128 + lane * 4;
    asm volatile("red.global.add.v4.f32 [%0], {%1,%2,%3,%4};"
                 :: "l"(dst), "f"(v.x), "f"(v.y), "f"(v.z), "f"(v.w)
                 : "memory");
}

// out[i] = relu(in[i] + bias[i % C])
__global__ void k_bias_relu(const float* __restrict__ in,
                            const float* __restrict__ bias,
                            float* __restrict__ out, int total, int C) {
    int i = blockIdx.x * blockDim.x + threadIdx.x;
    if (i < total) out[i] = fmaxf(in[i] + bias[i % C], 0.f);
}

// ---------------------------------------------------------------------------
// h2[N,12] = out1[N,128] @ W2[128,12]   (out1 lives in g_h1)
// blockDim must be multiple of 12 (384)
// ---------------------------------------------------------------------------
__global__ void k_gemm_n12(const float* __restrict__ W2, int n) {
    __shared__ float sW[128 * 12];
    for (int i = threadIdx.x; i < 128 * 12; i += 384) sW[i] = W2[i];
    __syncthreads();
    int t = blockIdx.x * 384 + threadIdx.x;
    if (t >= n * 12) return;
    int node = t / 12;
    int j = t - node * 12;
    const float* a = g_h1 + (size_t)node * 128;
    float s = 0.f;
#pragma unroll 8
    for (int k = 0; k < 128; k++) s += a[k] * sW[k * 12 + j];
    g_h2[t] = s;
}

// ---------------------------------------------------------------------------
// GCN message passing, layer 2 (12-dim features = 3 float4 per node)
// ---------------------------------------------------------------------------
__global__ void k_selfloop12(int n) {
    int idx = blockIdx.x * blockDim.x + threadIdx.x;  // over n*3 float4s
    if (idx >= n * 3) return;
    int node = idx / 3;
    float d = g_dinv[node];
    d = d * d;
    float4 v = ((const float4*)g_h2)[idx];
    v.x *= d; v.y *= d; v.z *= d; v.w *= d;
    ((float4*)g_agg2)[idx] = v;
}

// 3 threads per edge, float4 each
__global__ void k_edge_scatter12(const int* __restrict__ row,
                                 const int* __restrict__ col, int E) {
    int t = blockIdx.x * blockDim.x + threadIdx.x;
    int e = t / 3;
    if (e >= E) return;
    int g = t - e * 3;
    int r = row[e], c = col[e];
    float nrm = g_dinv[r] * g_dinv[c];
    float4 v = *(const float4*)(g_h2 + (size_t)r * 12 + g * 4);
    v.x *= nrm; v.y *= nrm; v.z *= nrm; v.w *= nrm;
    float* dst = g_agg2 + (size_t)c * 12 + g * 4;
    asm volatile("red.global.add.v4.f32 [%0], {%1,%2,%3,%4};"
                 :: "l"(dst), "f"(v.x), "f"(v.y), "f"(v.z), "f"(v.w)
                 : "memory");
}

// ---------------------------------------------------------------------------
// m1[N,512] = relu(out2[N,12] @ L1[12,512] + lb1)   (out2 lives in g_h2)
// Block handles 64 nodes; L1 cached in smem (24 KB).
// ---------------------------------------------------------------------------
__global__ void __launch_bounds__(256) k_mlp1(
    const float* __restrict__ L1, const float* __restrict__ lb1, int n) {
    __shared__ float sL[12 * 512];
    __shared__ float sb[512];
    __shared__ float sh[64 * 12];
    int node0 = blockIdx.x * 64;
    for (int i = threadIdx.x; i < 12 * 512; i += 256) sL[i] = L1[i];
    for (int i = threadIdx.x; i < 512; i += 256) sb[i] = lb1[i];
    for (int i = threadIdx.x; i < 64 * 12; i += 256) {
        int nn = node0 + i / 12;
        sh[i] = (nn < n) ? g_h2[(size_t)node0 * 12 + i] : 0.f;
    }
    __syncthreads();
    for (int idx = threadIdx.x; idx < 64 * 512; idx += 256) {
        int ln = idx >> 9;
        int j = idx & 511;
        int node = node0 + ln;
        if (node >= n) continue;
        float s = sb[j];
#pragma unroll
        for (int k = 0; k < 12; k++) s += sh[ln * 12 + k] * sL[k * 512 + j];
        g_m1[(size_t)node * 512 + j] = fmaxf(s, 0.f);
    }
}

// ---------------------------------------------------------------------------
// out[N,2] = m2[N,512] @ L3[512,2] + lb3. One warp per node.
// ---------------------------------------------------------------------------
__global__ void k_final(const float* __restrict__ L3,
                        const float* __restrict__ lb3,
                        float* __restrict__ out, int n) {
    __shared__ float sL[1024];
    for (int i = threadIdx.x; i < 1024; i += blockDim.x) sL[i] = L3[i];
    __syncthreads();
    int w = (blockIdx.x * blockDim.x + threadIdx.x) >> 5;
    int lane = threadIdx.x & 31;
    if (w >= n) return;
    const float* a = g_m2 + (size_t)w * 512;
    float s0 = 0.f, s1 = 0.f;
#pragma unroll 4
    for (int k = lane; k < 512; k += 32) {
        float v = a[k];
        s0 += v * sL[k * 2 + 0];
        s1 += v * sL[k * 2 + 1];
    }
#pragma unroll
    for (int o = 16; o > 0; o >>= 1) {
        s0 += __shfl_down_sync(0xffffffffu, s0, o);
        s1 += __shfl_down_sync(0xffffffffu, s1, o);
    }
    if (lane == 0) {
        out[(size_t)w * 2 + 0] = s0 + lb3[0];
        out[(size_t)w * 2 + 1] = s1 + lb3[1];
    }
}

// ---------------------------------------------------------------------------
// Launch
// ---------------------------------------------------------------------------
extern "C" void kernel_launch(void* const* d_in, const int* in_sizes, int n_in,
                              void* d_out, int out_size) {
    const float* x   = (const float*)d_in[0];
    const int*   ei  = (const int*)  d_in[1];
    const float* W1  = (const float*)d_in[2];
    const float* b1  = (const float*)d_in[3];
    const float* W2  = (const float*)d_in[4];
    const float* b2  = (const float*)d_in[5];
    const float* L1  = (const float*)d_in[6];
    const float* lb1 = (const float*)d_in[7];
    const float* L2  = (const float*)d_in[8];
    const float* lb2 = (const float*)d_in[9];
    const float* L3  = (const float*)d_in[10];
    const float* lb3 = (const float*)d_in[11];
    float* out = (float*)d_out;

    const int N = in_sizes[0] / 256;
    const int E = in_sizes[1] / 2;
    const int* row = ei;
    const int* col = ei + E;

    // Device addresses of scratch symbols (host-side; capture-safe)
    float *p_h1, *p_agg1, *p_h2, *p_agg2, *p_m1, *p_m2;
    cudaGetSymbolAddress((void**)&p_h1,   g_h1);
    cudaGetSymbolAddress((void**)&p_agg1, g_agg1);
    cudaGetSymbolAddress((void**)&p_h2,   g_h2);
    cudaGetSymbolAddress((void**)&p_agg2, g_agg2);
    cudaGetSymbolAddress((void**)&p_m1,   g_m1);
    cudaGetSymbolAddress((void**)&p_m2,   g_m2);

    // --- degree / normalization ---
    k_deg_init <<<(N + 255) / 256, 256>>>(N);
    k_deg_edges<<<(E + 255) / 256, 256>>>(col, E);
    k_deg_rsqrt<<<(N + 255) / 256, 256>>>(N);

    // --- GCN layer 1: h1 = x @ W1; agg; relu(+b1) ---
    k_sgemm<false><<<dim3((N + 127) / 128, 1), 256>>>(x, W1, nullptr, p_h1,
                                                      N, 128, 256);
    k_selfloop128<<<(N * 32 + 255) / 256, 256>>>(N);
    k_edge_scatter128<<<(E * 32 + 255) / 256, 256>>>(row, col, E);
    k_bias_relu<<<(N * 128 + 255) / 256, 256>>>(p_agg1, b1, p_h1, N * 128, 128);

    // --- GCN layer 2: h2 = out1 @ W2; agg; relu(+b2) ---
    k_gemm_n12<<<(N * 12 + 383) / 384, 384>>>(W2, N);
    k_selfloop12<<<(N * 3 + 255) / 256, 256>>>(N);
    k_edge_scatter12<<<(E * 3 + 255) / 256, 256>>>(row, col, E);
    k_bias_relu<<<(N * 12 + 255) / 256, 256>>>(p_agg2, b2, p_h2, N * 12, 12);

    // --- MLP ---
    k_mlp1<<<(N + 63) / 64, 256>>>(L1, lb1, N);
    k_sgemm<true><<<dim3((N + 127) / 128, 4), 256>>>(p_m1, L2, lb2, p_m2,
                                                     N, 512, 512);
    k_final<<<(N * 32 + 255) / 256, 256>>>(L3, lb3, out, N);
}

// round 3
// speedup vs baseline: 1.3910x; 1.3910x over previous
#include <cuda_runtime.h>
#include <cuda_bf16.h>
#include <cstdint>

// ---------------------------------------------------------------------------
// Problem constants: N=50000, E=800000, F=256
// ---------------------------------------------------------------------------
#define NMAX 50176   // 50000 rounded up to multiple of 128

// Scratch (device globals; allocation-free kernel_launch)
__device__ float g_dinv[NMAX];
__device__ float g_h1  [(size_t)NMAX * 128];
__device__ float g_agg1[(size_t)NMAX * 128];
__device__ float g_h2  [(size_t)NMAX * 12];
__device__ float g_agg2[(size_t)NMAX * 12];
__device__ __nv_bfloat16 g_xh [(size_t)NMAX * 256];   // hi(x)
__device__ __nv_bfloat16 g_xl [(size_t)NMAX * 256];   // lo(x)
__device__ __nv_bfloat16 g_w1th[128 * 256];           // hi(W1^T) [n,k]
__device__ __nv_bfloat16 g_w1tl[128 * 256];           // lo(W1^T)
__device__ __nv_bfloat16 g_m1h[(size_t)NMAX * 512];   // hi(m1)
__device__ __nv_bfloat16 g_m1l[(size_t)NMAX * 512];   // lo(m1)
__device__ __nv_bfloat16 g_bth[512 * 512];            // hi(L2^T) [n,k]
__device__ __nv_bfloat16 g_btl[512 * 512];            // lo(L2^T)
__device__ float g_m2  [(size_t)NMAX * 512];

// ---------------------------------------------------------------------------
// PTX helpers (sm_80-era MMA path; no tcgen05 — compute_103-safe)
// ---------------------------------------------------------------------------
__device__ __forceinline__ uint32_t smem_u32(const void* p) {
    return (uint32_t)__cvta_generic_to_shared(p);
}
__device__ __forceinline__ void ldm_x4(uint32_t* r, uint32_t addr) {
    asm volatile("ldmatrix.sync.aligned.m8n8.x4.shared.b16 {%0,%1,%2,%3}, [%4];"
                 : "=r"(r[0]), "=r"(r[1]), "=r"(r[2]), "=r"(r[3]) : "r"(addr));
}
__device__ __forceinline__ void mma_bf16(float* c, const uint32_t* a,
                                         uint32_t b0, uint32_t b1) {
    asm volatile(
        "mma.sync.aligned.m16n8k16.row.col.f32.bf16.bf16.f32 "
        "{%0,%1,%2,%3}, {%4,%5,%6,%7}, {%8,%9}, {%0,%1,%2,%3};"
        : "+f"(c[0]), "+f"(c[1]), "+f"(c[2]), "+f"(c[3])
        : "r"(a[0]), "r"(a[1]), "r"(a[2]), "r"(a[3]), "r"(b0), "r"(b1));
}
#define CP_ASYNC16(dst, src) \
    asm volatile("cp.async.cg.shared.global [%0], [%1], 16;" :: "r"(dst), "l"(src))
#define CP_WAIT_ALL() \
    asm volatile("cp.async.commit_group;\ncp.async.wait_group 0;" ::: "memory")

// ---------------------------------------------------------------------------
// Degree / normalization
// ---------------------------------------------------------------------------
__global__ void k_deg_init(int n) {
    int i = blockIdx.x * blockDim.x + threadIdx.x;
    if (i < n) g_dinv[i] = 1.0f;
}
__global__ void k_deg_edges(const int* __restrict__ col, int E) {
    int e = blockIdx.x * blockDim.x + threadIdx.x;
    if (e < E) atomicAdd(&g_dinv[col[e]], 1.0f);
}
__global__ void k_deg_rsqrt(int n) {
    int i = blockIdx.x * blockDim.x + threadIdx.x;
    if (i < n) g_dinv[i] = rsqrtf(g_dinv[i]);
}

// ---------------------------------------------------------------------------
// Splits / transposed-weight prep
// ---------------------------------------------------------------------------
// x[N,256] -> xh/xl [NMAX,256] bf16, zero-padded rows
__global__ void k_split_x(const float* __restrict__ x, int n) {
    int i = blockIdx.x * blockDim.x + threadIdx.x;
    if (i >= NMAX * 256) return;
    int node = i >> 8;
    float v = (node < n) ? x[i] : 0.f;
    __nv_bfloat16 h = __float2bfloat16(v);
    g_xh[i] = h;
    g_xl[i] = __float2bfloat16(v - __bfloat162float(h));
}

// W[K,N] -> BT hi/lo [N,K]
__global__ void k_bt_prep(const float* __restrict__ W,
                          __nv_bfloat16* __restrict__ th,
                          __nv_bfloat16* __restrict__ tl, int K, int N) {
    int i = blockIdx.x * blockDim.x + threadIdx.x;
    if (i >= N * K) return;
    int n = i / K, k = i - n * K;
    float v = W[(size_t)k * N + n];
    __nv_bfloat16 h = __float2bfloat16(v);
    th[i] = h;
    tl[i] = __float2bfloat16(v - __bfloat162float(h));
}

// ---------------------------------------------------------------------------
// bf16 split-MMA GEMM: C[M,N] = [relu](Ah+Al)@(Bh+Bl)^T [+ bias]
//   - A hi/lo: [M,K] bf16 row-major (M multiple of 128, zero-padded)
//   - BT hi/lo: [N,K] bf16 row-major (k-contiguous) — i.e. B col-major
//   - 3-term: AhBh + AhBl + AlBh
// CTA: 128x128 tile, 256 threads (8 warps, 4x2), warp tile 32x64, k-tile 32.
// ---------------------------------------------------------------------------
#define SMP 40   // smem row stride in bf16 elems (80B: ldmatrix conflict-free)

template <bool EPI>
__global__ void __launch_bounds__(256) k_mma(
    const __nv_bfloat16* __restrict__ Ah, const __nv_bfloat16* __restrict__ Al,
    const __nv_bfloat16* __restrict__ BTh, const __nv_bfloat16* __restrict__ BTl,
    const float* __restrict__ bias, float* __restrict__ C, int M, int N, int K)
{
    __shared__ __align__(16) __nv_bfloat16 sAh[128 * SMP];
    __shared__ __align__(16) __nv_bfloat16 sAl[128 * SMP];
    __shared__ __align__(16) __nv_bfloat16 sBh[128 * SMP];
    __shared__ __align__(16) __nv_bfloat16 sBl[128 * SMP];

    const int tid = threadIdx.x;
    const int lane = tid & 31;
    const int wid = tid >> 5;
    const int wm = (wid & 3) * 32;   // warp m offset in tile
    const int wn = (wid >> 2) * 64;  // warp n offset in tile
    const int m0 = blockIdx.x * 128;
    const int n0 = blockIdx.y * 128;

    const uint32_t sAh_b = smem_u32(sAh);
    const uint32_t sAl_b = smem_u32(sAl);
    const uint32_t sBh_b = smem_u32(sBh);
    const uint32_t sBl_b = smem_u32(sBl);

    float acc[2][8][4];
#pragma unroll
    for (int i = 0; i < 2; i++)
#pragma unroll
        for (int j = 0; j < 8; j++)
#pragma unroll
            for (int t = 0; t < 4; t++) acc[i][j][t] = 0.f;

    // ldmatrix source offsets (within tile, element units)
    const int a_lr = lane & 15, a_lc = (lane >> 4) * 8;
    const int b_lr = (lane & 7) + ((lane >> 4) << 3);
    const int b_lc = ((lane >> 3) & 1) * 8;

    for (int kt = 0; kt < K; kt += 32) {
        // ---- load k-tile: 4 matrices of 128x32 bf16 via cp.async ----
#pragma unroll
        for (int j = 0; j < 2; j++) {
            int s = tid + j * 256;          // 0..511
            int row = s >> 2, q = s & 3;
            uint32_t so = (uint32_t)(row * SMP + q * 8) * 2;
            size_t ga = (size_t)(m0 + row) * K + kt + q * 8;
            size_t gb = (size_t)(n0 + row) * K + kt + q * 8;
            CP_ASYNC16(sAh_b + so, Ah + ga);
            CP_ASYNC16(sAl_b + so, Al + ga);
            CP_ASYNC16(sBh_b + so, BTh + gb);
            CP_ASYNC16(sBl_b + so, BTl + gb);
        }
        CP_WAIT_ALL();
        __syncthreads();

#pragma unroll
        for (int ks = 0; ks < 2; ks++) {
            uint32_t ah[2][4], al[2][4], bh[4][4], bl[4][4];
#pragma unroll
            for (int mt = 0; mt < 2; mt++) {
                uint32_t off = (uint32_t)((wm + mt * 16 + a_lr) * SMP
                                          + ks * 16 + a_lc) * 2;
                ldm_x4(ah[mt], sAh_b + off);
                ldm_x4(al[mt], sAl_b + off);
            }
#pragma unroll
            for (int p = 0; p < 4; p++) {
                uint32_t off = (uint32_t)((wn + p * 16 + b_lr) * SMP
                                          + ks * 16 + b_lc) * 2;
                ldm_x4(bh[p], sBh_b + off);
                ldm_x4(bl[p], sBl_b + off);
            }
#pragma unroll
            for (int mt = 0; mt < 2; mt++)
#pragma unroll
                for (int nt = 0; nt < 8; nt++) {
                    int p = nt >> 1, h = (nt & 1) * 2;
                    mma_bf16(acc[mt][nt], ah[mt], bh[p][h], bh[p][h + 1]);
                    mma_bf16(acc[mt][nt], ah[mt], bl[p][h], bl[p][h + 1]);
                    mma_bf16(acc[mt][nt], al[mt], bh[p][h], bh[p][h + 1]);
                }
        }
        __syncthreads();
    }

    // ---- epilogue: direct global writes (M padded; no guards) ----
#pragma unroll
    for (int mt = 0; mt < 2; mt++) {
#pragma unroll
        for (int r = 0; r < 2; r++) {
            int m = m0 + wm + mt * 16 + (lane >> 2) + r * 8;
#pragma unroll
            for (int nt = 0; nt < 8; nt++) {
                int n = n0 + wn + nt * 8 + (lane & 3) * 2;
                float v0 = acc[mt][nt][r * 2 + 0];
                float v1 = acc[mt][nt][r * 2 + 1];
                if (EPI) {
                    v0 = fmaxf(v0 + bias[n + 0], 0.f);
                    v1 = fmaxf(v1 + bias[n + 1], 0.f);
                }
                *(float2*)(C + (size_t)m * N + n) = make_float2(v0, v1);
            }
        }
    }
}

// ---------------------------------------------------------------------------
// GCN message passing, layer 1 (128-dim)
// ---------------------------------------------------------------------------
__global__ void k_selfloop128(int n) {
    int idx = blockIdx.x * blockDim.x + threadIdx.x;
    if (idx >= n * 32) return;
    int node = idx >> 5;
    float d = g_dinv[node]; d = d * d;
    float4 v = ((const float4*)g_h1)[idx];
    v.x *= d; v.y *= d; v.z *= d; v.w *= d;
    ((float4*)g_agg1)[idx] = v;
}
__global__ void k_edge_scatter128(const int* __restrict__ row,
                                  const int* __restrict__ col, int E) {
    int gt = blockIdx.x * blockDim.x + threadIdx.x;
    int e = gt >> 5;
    if (e >= E) return;
    int lane = gt & 31;
    int r = row[e], c = col[e];
    float nrm = g_dinv[r] * g_dinv[c];
    float4 v = ((const float4*)(g_h1 + (size_t)r * 128))[lane];
    v.x *= nrm; v.y *= nrm; v.z *= nrm; v.w *= nrm;
    float* dst = g_agg1 + (size_t)c * 128 + lane * 4;
    asm volatile("red.global.add.v4.f32 [%0], {%1,%2,%3,%4};"
                 :: "l"(dst), "f"(v.x), "f"(v.y), "f"(v.z), "f"(v.w) : "memory");
}
__global__ void k_bias_relu(const float* __restrict__ in,
                            const float* __restrict__ bias,
                            float* __restrict__ out, int total, int C) {
    int i = blockIdx.x * blockDim.x + threadIdx.x;
    if (i < total) out[i] = fmaxf(in[i] + bias[i % C], 0.f);
}

// ---------------------------------------------------------------------------
// h2[N,12] = out1[N,128] @ W2[128,12]
// ---------------------------------------------------------------------------
__global__ void k_gemm_n12(const float* __restrict__ W2, int n) {
    __shared__ float sW[128 * 12];
    for (int i = threadIdx.x; i < 128 * 12; i += 384) sW[i] = W2[i];
    __syncthreads();
    int t = blockIdx.x * 384 + threadIdx.x;
    if (t >= n * 12) return;
    int node = t / 12;
    int j = t - node * 12;
    const float* a = g_h1 + (size_t)node * 128;
    float s = 0.f;
#pragma unroll 8
    for (int k = 0; k < 128; k++) s += a[k] * sW[k * 12 + j];
    g_h2[t] = s;
}

// ---------------------------------------------------------------------------
// GCN message passing, layer 2 (12-dim)
// ---------------------------------------------------------------------------
__global__ void k_selfloop12(int n) {
    int idx = blockIdx.x * blockDim.x + threadIdx.x;
    if (idx >= n * 3) return;
    int node = idx / 3;
    float d = g_dinv[node]; d = d * d;
    float4 v = ((const float4*)g_h2)[idx];
    v.x *= d; v.y *= d; v.z *= d; v.w *= d;
    ((float4*)g_agg2)[idx] = v;
}
__global__ void k_edge_scatter12(const int* __restrict__ row,
                                 const int* __restrict__ col, int E) {
    int t = blockIdx.x * blockDim.x + threadIdx.x;
    int e = t / 3;
    if (e >= E) return;
    int g = t - e * 3;
    int r = row[e], c = col[e];
    float nrm = g_dinv[r] * g_dinv[c];
    float4 v = *(const float4*)(g_h2 + (size_t)r * 12 + g * 4);
    v.x *= nrm; v.y *= nrm; v.z *= nrm; v.w *= nrm;
    float* dst = g_agg2 + (size_t)c * 12 + g * 4;
    asm volatile("red.global.add.v4.f32 [%0], {%1,%2,%3,%4};"
                 :: "l"(dst), "f"(v.x), "f"(v.y), "f"(v.z), "f"(v.w) : "memory");
}

// ---------------------------------------------------------------------------
// m1 = relu(out2[N,12] @ L1[12,512] + lb1), written as bf16 hi/lo split.
// Pads rows [n, NMAX) with zeros.
// ---------------------------------------------------------------------------
__global__ void __launch_bounds__(256) k_mlp1_split(
    const float* __restrict__ L1, const float* __restrict__ lb1, int n) {
    __shared__ float sL[12 * 512];
    __shared__ float sb[512];
    __shared__ float sh[64 * 12];
    int node0 = blockIdx.x * 64;
    for (int i = threadIdx.x; i < 12 * 512; i += 256) sL[i] = L1[i];
    for (int i = threadIdx.x; i < 512; i += 256) sb[i] = lb1[i];
    for (int i = threadIdx.x; i < 64 * 12; i += 256) {
        int nn = node0 + i / 12;
        sh[i] = (nn < n) ? g_h2[(size_t)node0 * 12 + i] : 0.f;
    }
    __syncthreads();
    for (int idx = threadIdx.x; idx < 64 * 512; idx += 256) {
        int ln = idx >> 9;
        int j = idx & 511;
        int node = node0 + ln;
        float s;
        if (node < n) {
            s = sb[j];
#pragma unroll
            for (int k = 0; k < 12; k++) s += sh[ln * 12 + k] * sL[k * 512 + j];
            s = fmaxf(s, 0.f);
        } else {
            s = 0.f;
        }
        __nv_bfloat16 h = __float2bfloat16(s);
        float rem = s - __bfloat162float(h);
        size_t o = (size_t)node * 512 + j;
        g_m1h[o] = h;
        g_m1l[o] = __float2bfloat16(rem);
    }
}

// ---------------------------------------------------------------------------
// out[N,2] = m2[N,512] @ L3[512,2] + lb3. One warp per node.
// ---------------------------------------------------------------------------
__global__ void k_final(const float* __restrict__ L3,
                        const float* __restrict__ lb3,
                        float* __restrict__ out, int n) {
    __shared__ float sL[1024];
    for (int i = threadIdx.x; i < 1024; i += blockDim.x) sL[i] = L3[i];
    __syncthreads();
    int w = (blockIdx.x * blockDim.x + threadIdx.x) >> 5;
    int lane = threadIdx.x & 31;
    if (w >= n) return;
    const float* a = g_m2 + (size_t)w * 512;
    float s0 = 0.f, s1 = 0.f;
#pragma unroll 4
    for (int k = lane; k < 512; k += 32) {
        float v = a[k];
        s0 += v * sL[k * 2 + 0];
        s1 += v * sL[k * 2 + 1];
    }
#pragma unroll
    for (int o = 16; o > 0; o >>= 1) {
        s0 += __shfl_down_sync(0xffffffffu, s0, o);
        s1 += __shfl_down_sync(0xffffffffu, s1, o);
    }
    if (lane == 0) {
        out[(size_t)w * 2 + 0] = s0 + lb3[0];
        out[(size_t)w * 2 + 1] = s1 + lb3[1];
    }
}

// ---------------------------------------------------------------------------
// Launch
// ---------------------------------------------------------------------------
extern "C" void kernel_launch(void* const* d_in, const int* in_sizes, int n_in,
                              void* d_out, int out_size) {
    const float* x   = (const float*)d_in[0];
    const int*   ei  = (const int*)  d_in[1];
    const float* W1  = (const float*)d_in[2];
    const float* b1  = (const float*)d_in[3];
    const float* W2  = (const float*)d_in[4];
    const float* b2  = (const float*)d_in[5];
    const float* L1  = (const float*)d_in[6];
    const float* lb1 = (const float*)d_in[7];
    const float* L2  = (const float*)d_in[8];
    const float* lb2 = (const float*)d_in[9];
    const float* L3  = (const float*)d_in[10];
    const float* lb3 = (const float*)d_in[11];
    float* out = (float*)d_out;

    const int N = in_sizes[0] / 256;
    const int E = in_sizes[1] / 2;
    const int* row = ei;
    const int* col = ei + E;

    float *p_h1, *p_agg1, *p_h2, *p_agg2, *p_m2;
    __nv_bfloat16 *p_xh, *p_xl, *p_w1th, *p_w1tl, *p_m1h, *p_m1l, *p_bth, *p_btl;
    cudaGetSymbolAddress((void**)&p_h1,   g_h1);
    cudaGetSymbolAddress((void**)&p_agg1, g_agg1);
    cudaGetSymbolAddress((void**)&p_h2,   g_h2);
    cudaGetSymbolAddress((void**)&p_agg2, g_agg2);
    cudaGetSymbolAddress((void**)&p_xh,   g_xh);
    cudaGetSymbolAddress((void**)&p_xl,   g_xl);
    cudaGetSymbolAddress((void**)&p_w1th, g_w1th);
    cudaGetSymbolAddress((void**)&p_w1tl, g_w1tl);
    cudaGetSymbolAddress((void**)&p_m1h,  g_m1h);
    cudaGetSymbolAddress((void**)&p_m1l,  g_m1l);
    cudaGetSymbolAddress((void**)&p_bth,  g_bth);
    cudaGetSymbolAddress((void**)&p_btl,  g_btl);
    cudaGetSymbolAddress((void**)&p_m2,   g_m2);

    // --- degree / normalization ---
    k_deg_init <<<(N + 255) / 256, 256>>>(N);
    k_deg_edges<<<(E + 255) / 256, 256>>>(col, E);
    k_deg_rsqrt<<<(N + 255) / 256, 256>>>(N);

    // --- GCN layer 1: h1 = x @ W1 via bf16-split HMMA ---
    k_split_x<<<(NMAX * 256 + 255) / 256, 256>>>(x, N);
    k_bt_prep<<<(128 * 256 + 255) / 256, 256>>>(W1, p_w1th, p_w1tl, 256, 128);
    k_mma<false><<<dim3(NMAX / 128, 1), 256>>>(p_xh, p_xl, p_w1th, p_w1tl,
                                               nullptr, p_h1, NMAX, 128, 256);
    k_selfloop128<<<(N * 32 + 255) / 256, 256>>>(N);
    k_edge_scatter128<<<(E * 32 + 255) / 256, 256>>>(row, col, E);
    k_bias_relu<<<(N * 128 + 255) / 256, 256>>>(p_agg1, b1, p_h1, N * 128, 128);

    // --- GCN layer 2 ---
    k_gemm_n12<<<(N * 12 + 383) / 384, 384>>>(W2, N);
    k_selfloop12<<<(N * 3 + 255) / 256, 256>>>(N);
    k_edge_scatter12<<<(E * 3 + 255) / 256, 256>>>(row, col, E);
    k_bias_relu<<<(N * 12 + 255) / 256, 256>>>(p_agg2, b2, p_h2, N * 12, 12);

    // --- MLP ---
    k_mlp1_split<<<NMAX / 64, 256>>>(L1, lb1, N);
    k_bt_prep<<<(512 * 512 + 255) / 256, 256>>>(L2, p_bth, p_btl, 512, 512);
    k_mma<true><<<dim3(NMAX / 128, 4), 256>>>(p_m1h, p_m1l, p_bth, p_btl,
                                              lb2, p_m2, NMAX, 512, 512);
    k_final<<<(N * 32 + 255) / 256, 256>>>(L3, lb3, out, N);
}

// round 4
// speedup vs baseline: 1.8434x; 1.3252x over previous
#include <cuda_runtime.h>
#include <cuda_bf16.h>
#include <cstdint>

// ---------------------------------------------------------------------------
// Problem constants: N=50000, E=800000, F=256
// ---------------------------------------------------------------------------
#define NMAX 50176   // 50000 rounded up to multiple of 128

// Scratch (device globals; allocation-free kernel_launch)
__device__ float g_dinv[NMAX];
__device__ float g_h1  [(size_t)NMAX * 128];
__device__ float g_agg1[(size_t)NMAX * 128];
__device__ float g_h2  [(size_t)NMAX * 12];
__device__ float g_agg2[(size_t)NMAX * 12];
__device__ __nv_bfloat16 g_xh [(size_t)NMAX * 256];   // hi(x)
__device__ __nv_bfloat16 g_xl [(size_t)NMAX * 256];   // lo(x)
__device__ __nv_bfloat16 g_w1th[128 * 256];           // hi(W1^T) [n,k]
__device__ __nv_bfloat16 g_w1tl[128 * 256];           // lo(W1^T)
__device__ __nv_bfloat16 g_m1h[(size_t)NMAX * 512];   // hi(m1)
__device__ __nv_bfloat16 g_m1l[(size_t)NMAX * 512];   // lo(m1)
__device__ __nv_bfloat16 g_bth[512 * 512];            // hi(L2^T) [n,k]
__device__ __nv_bfloat16 g_btl[512 * 512];            // lo(L2^T)

// ---------------------------------------------------------------------------
// PTX helpers (sm_80-era MMA path; compute_103-safe)
// ---------------------------------------------------------------------------
__device__ __forceinline__ uint32_t smem_u32(const void* p) {
    return (uint32_t)__cvta_generic_to_shared(p);
}
__device__ __forceinline__ void ldm_x4(uint32_t* r, uint32_t addr) {
    asm volatile("ldmatrix.sync.aligned.m8n8.x4.shared.b16 {%0,%1,%2,%3}, [%4];"
                 : "=r"(r[0]), "=r"(r[1]), "=r"(r[2]), "=r"(r[3]) : "r"(addr));
}
__device__ __forceinline__ void mma_bf16(float* c, const uint32_t* a,
                                         uint32_t b0, uint32_t b1) {
    asm volatile(
        "mma.sync.aligned.m16n8k16.row.col.f32.bf16.bf16.f32 "
        "{%0,%1,%2,%3}, {%4,%5,%6,%7}, {%8,%9}, {%0,%1,%2,%3};"
        : "+f"(c[0]), "+f"(c[1]), "+f"(c[2]), "+f"(c[3])
        : "r"(a[0]), "r"(a[1]), "r"(a[2]), "r"(a[3]), "r"(b0), "r"(b1));
}
#define CP_ASYNC16(dst, src) \
    asm volatile("cp.async.cg.shared.global [%0], [%1], 16;" :: "r"(dst), "l"(src))
#define CP_COMMIT() asm volatile("cp.async.commit_group;" ::: "memory")
#define CP_WAIT1()  asm volatile("cp.async.wait_group 1;" ::: "memory")

__device__ __forceinline__ uint32_t pk_bf2(__nv_bfloat16 a, __nv_bfloat16 b) {
    __nv_bfloat162 t(a, b);
    return *reinterpret_cast<uint32_t*>(&t);
}

// ---------------------------------------------------------------------------
// Degree / normalization
// ---------------------------------------------------------------------------
__global__ void k_deg_init(int n) {
    int i = blockIdx.x * blockDim.x + threadIdx.x;
    if (i < n) g_dinv[i] = 1.0f;
}
__global__ void k_deg_edges(const int* __restrict__ col, int E) {
    int e = blockIdx.x * blockDim.x + threadIdx.x;
    if (e < E) atomicAdd(&g_dinv[col[e]], 1.0f);
}
__global__ void k_deg_rsqrt(int n) {
    int i = blockIdx.x * blockDim.x + threadIdx.x;
    if (i < n) g_dinv[i] = rsqrtf(g_dinv[i]);
}

// ---------------------------------------------------------------------------
// Splits / transposed-weight prep
// ---------------------------------------------------------------------------
// x[N,256] -> xh/xl [NMAX,256] bf16, vectorized (float4 in, uint2 out)
__global__ void k_split_x(const float* __restrict__ x, int n) {
    int i = blockIdx.x * blockDim.x + threadIdx.x;   // over NMAX*64 float4s
    if (i >= NMAX * 64) return;
    int node = i >> 6;
    float4 v = (node < n) ? ((const float4*)x)[i]
                          : make_float4(0.f, 0.f, 0.f, 0.f);
    __nv_bfloat16 h0 = __float2bfloat16(v.x), h1 = __float2bfloat16(v.y);
    __nv_bfloat16 h2 = __float2bfloat16(v.z), h3 = __float2bfloat16(v.w);
    uint2 H = make_uint2(pk_bf2(h0, h1), pk_bf2(h2, h3));
    ((uint2*)g_xh)[i] = H;
    float l0 = v.x - __bfloat162float(h0), l1 = v.y - __bfloat162float(h1);
    float l2 = v.z - __bfloat162float(h2), l3 = v.w - __bfloat162float(h3);
    uint2 L = make_uint2(pk_bf2(__float2bfloat16(l0), __float2bfloat16(l1)),
                         pk_bf2(__float2bfloat16(l2), __float2bfloat16(l3)));
    ((uint2*)g_xl)[i] = L;
}

// W[K,N] -> BT hi/lo [N,K]
__global__ void k_bt_prep(const float* __restrict__ W,
                          __nv_bfloat16* __restrict__ th,
                          __nv_bfloat16* __restrict__ tl, int K, int N) {
    int i = blockIdx.x * blockDim.x + threadIdx.x;
    if (i >= N * K) return;
    int n = i / K, k = i - n * K;
    float v = W[(size_t)k * N + n];
    __nv_bfloat16 h = __float2bfloat16(v);
    th[i] = h;
    tl[i] = __float2bfloat16(v - __bfloat162float(h));
}

// out[i] = lb3 (bias pre-init for fused final layer)
__global__ void k_out_init(const float* __restrict__ lb3,
                           float* __restrict__ out, int n) {
    int i = blockIdx.x * blockDim.x + threadIdx.x;
    if (i < n) ((float2*)out)[i] = make_float2(lb3[0], lb3[1]);
}

// ---------------------------------------------------------------------------
// bf16 split-MMA GEMM, 2-stage cp.async pipeline.
//   C[M,N] = (Ah+Al)@(Bh+Bl)^T  (3-term: AhBh + AhBl + AlBh)
// CTA 128x128 tile, 256 threads (4x2 warps), warp tile 32x64, k-tile 32.
// MODE 0: store C.
// MODE 1: store C and C2 = C * dinv[m]^2   (layer-1: h1 + selfloop fused)
// MODE 2: no C store; relu(C+bias) projected through L3 -> RED into out
// ---------------------------------------------------------------------------
#define SMP 40                      // smem row stride (elems); 80B rows
#define MAT_B (128 * SMP * 2)       // one 128x32 bf16 matrix region: 10240 B
#define BUF_B (4 * MAT_B)           // Ah,Al,Bh,Bl per stage: 40960 B
#define DSM_B (2 * BUF_B + 1024)    // + L3 tile (128x2 f32)

template <int MODE>
__global__ void __launch_bounds__(256) k_mma(
    const __nv_bfloat16* __restrict__ Ah, const __nv_bfloat16* __restrict__ Al,
    const __nv_bfloat16* __restrict__ BTh, const __nv_bfloat16* __restrict__ BTl,
    const float* __restrict__ bias, float* __restrict__ C,
    const float* __restrict__ dinv, float* __restrict__ C2,
    const float* __restrict__ L3, float* __restrict__ outp,
    int Mreal, int N, int K)
{
    extern __shared__ char dsm[];
    const uint32_t sb = smem_u32(dsm);
    float* sL3 = (float*)(dsm + 2 * BUF_B);

    const int tid = threadIdx.x;
    const int lane = tid & 31;
    const int wid = tid >> 5;
    const int wm = (wid & 3) * 32;
    const int wn = (wid >> 2) * 64;
    const int m0 = blockIdx.x * 128;
    const int n0 = blockIdx.y * 128;

    if (MODE == 2) {
        // cache L3 rows [n0, n0+128)
        if (tid < 128) {
            float2 v = ((const float2*)L3)[n0 + tid];
            ((float2*)sL3)[tid] = v;
        }
    }

    float acc[2][8][4];
#pragma unroll
    for (int i = 0; i < 2; i++)
#pragma unroll
        for (int j = 0; j < 8; j++)
#pragma unroll
            for (int t = 0; t < 4; t++) acc[i][j][t] = 0.f;

    const int a_lr = lane & 15, a_lc = (lane >> 4) * 8;
    const int b_lr = (lane & 7) + ((lane >> 4) << 3);
    const int b_lc = ((lane >> 3) & 1) * 8;

    const int ntiles = K >> 5;

    // --- issue loads for tile kt into stage buf ---
    auto issue = [&](int kt, int buf) {
#pragma unroll
        for (int j = 0; j < 2; j++) {
            int s = tid + j * 256;
            int row = s >> 2, q = s & 3;
            uint32_t so = sb + buf * BUF_B + (uint32_t)(row * SMP + q * 8) * 2;
            size_t ga = (size_t)(m0 + row) * K + kt * 32 + q * 8;
            size_t gb = (size_t)(n0 + row) * K + kt * 32 + q * 8;
            CP_ASYNC16(so,             Ah + ga);
            CP_ASYNC16(so + MAT_B,     Al + ga);
            CP_ASYNC16(so + 2 * MAT_B, BTh + gb);
            CP_ASYNC16(so + 3 * MAT_B, BTl + gb);
        }
    };

    issue(0, 0);
    CP_COMMIT();

    for (int kt = 0; kt < ntiles; kt++) {
        const int cur = kt & 1;
        if (kt + 1 < ntiles) issue(kt + 1, cur ^ 1);
        CP_COMMIT();
        CP_WAIT1();
        __syncthreads();

        const uint32_t bA = sb + cur * BUF_B;
#pragma unroll
        for (int ks = 0; ks < 2; ks++) {
            uint32_t ah[2][4], al[2][4], bh[4][4], bl[4][4];
#pragma unroll
            for (int mt = 0; mt < 2; mt++) {
                uint32_t off = (uint32_t)((wm + mt * 16 + a_lr) * SMP
                                          + ks * 16 + a_lc) * 2;
                ldm_x4(ah[mt], bA + off);
                ldm_x4(al[mt], bA + MAT_B + off);
            }
#pragma unroll
            for (int p = 0; p < 4; p++) {
                uint32_t off = (uint32_t)((wn + p * 16 + b_lr) * SMP
                                          + ks * 16 + b_lc) * 2;
                ldm_x4(bh[p], bA + 2 * MAT_B + off);
                ldm_x4(bl[p], bA + 3 * MAT_B + off);
            }
#pragma unroll
            for (int mt = 0; mt < 2; mt++)
#pragma unroll
                for (int nt = 0; nt < 8; nt++) {
                    int p = nt >> 1, h = (nt & 1) * 2;
                    mma_bf16(acc[mt][nt], ah[mt], bh[p][h], bh[p][h + 1]);
                    mma_bf16(acc[mt][nt], ah[mt], bl[p][h], bl[p][h + 1]);
                    mma_bf16(acc[mt][nt], al[mt], bh[p][h], bh[p][h + 1]);
                }
        }
        __syncthreads();
    }

    // ---------------- epilogue ----------------
    if (MODE == 2) {
        float pr[4][2];
#pragma unroll
        for (int i = 0; i < 4; i++) { pr[i][0] = 0.f; pr[i][1] = 0.f; }
#pragma unroll
        for (int mt = 0; mt < 2; mt++)
#pragma unroll
            for (int r = 0; r < 2; r++) {
                int idx = mt * 2 + r;
#pragma unroll
                for (int nt = 0; nt < 8; nt++) {
                    int n = wn + nt * 8 + (lane & 3) * 2;  // tile-local col
                    float v0 = fmaxf(acc[mt][nt][r * 2 + 0] + bias[n0 + n], 0.f);
                    float v1 = fmaxf(acc[mt][nt][r * 2 + 1] + bias[n0 + n + 1], 0.f);
                    pr[idx][0] += v0 * sL3[2 * n + 0] + v1 * sL3[2 * (n + 1) + 0];
                    pr[idx][1] += v0 * sL3[2 * n + 1] + v1 * sL3[2 * (n + 1) + 1];
                }
            }
        // reduce across the 4 lanes of each quad (they cover distinct n)
#pragma unroll
        for (int i = 0; i < 4; i++) {
#pragma unroll
            for (int o = 1; o < 4; o <<= 1) {
                pr[i][0] += __shfl_xor_sync(0xffffffffu, pr[i][0], o);
                pr[i][1] += __shfl_xor_sync(0xffffffffu, pr[i][1], o);
            }
        }
        if ((lane & 3) == 0) {
#pragma unroll
            for (int mt = 0; mt < 2; mt++)
#pragma unroll
                for (int r = 0; r < 2; r++) {
                    int m = m0 + wm + mt * 16 + (lane >> 2) + r * 8;
                    if (m < Mreal) {
                        float* dst = outp + (size_t)m * 2;
                        asm volatile("red.global.add.v2.f32 [%0], {%1,%2};"
                                     :: "l"(dst), "f"(pr[mt * 2 + r][0]),
                                        "f"(pr[mt * 2 + r][1]) : "memory");
                    }
                }
        }
        return;
    }

#pragma unroll
    for (int mt = 0; mt < 2; mt++) {
#pragma unroll
        for (int r = 0; r < 2; r++) {
            int m = m0 + wm + mt * 16 + (lane >> 2) + r * 8;
            float d2 = 0.f;
            if (MODE == 1) { float d = dinv[m]; d2 = d * d; }
#pragma unroll
            for (int nt = 0; nt < 8; nt++) {
                int n = n0 + wn + nt * 8 + (lane & 3) * 2;
                float v0 = acc[mt][nt][r * 2 + 0];
                float v1 = acc[mt][nt][r * 2 + 1];
                *(float2*)(C + (size_t)m * N + n) = make_float2(v0, v1);
                if (MODE == 1)
                    *(float2*)(C2 + (size_t)m * N + n)
                        = make_float2(v0 * d2, v1 * d2);
            }
        }
    }
}

// ---------------------------------------------------------------------------
// GCN message passing, layer 1 (128-dim)
// ---------------------------------------------------------------------------
__global__ void k_edge_scatter128(const int* __restrict__ row,
                                  const int* __restrict__ col, int E) {
    int gt = blockIdx.x * blockDim.x + threadIdx.x;
    int e = gt >> 5;
    if (e >= E) return;
    int lane = gt & 31;
    int r = row[e], c = col[e];
    float nrm = g_dinv[r] * g_dinv[c];
    float4 v = ((const float4*)(g_h1 + (size_t)r * 128))[lane];
    v.x *= nrm; v.y *= nrm; v.z *= nrm; v.w *= nrm;
    float* dst = g_agg1 + (size_t)c * 128 + lane * 4;
    asm volatile("red.global.add.v4.f32 [%0], {%1,%2,%3,%4};"
                 :: "l"(dst), "f"(v.x), "f"(v.y), "f"(v.z), "f"(v.w) : "memory");
}
__global__ void k_bias_relu(const float* __restrict__ in,
                            const float* __restrict__ bias,
                            float* __restrict__ out, int total, int C) {
    int i = blockIdx.x * blockDim.x + threadIdx.x;
    if (i < total) out[i] = fmaxf(in[i] + bias[i % C], 0.f);
}

// ---------------------------------------------------------------------------
// h2[N,12] = out1[N,128] @ W2[128,12]
// ---------------------------------------------------------------------------
__global__ void k_gemm_n12(const float* __restrict__ W2, int n) {
    __shared__ float sW[128 * 12];
    for (int i = threadIdx.x; i < 128 * 12; i += 384) sW[i] = W2[i];
    __syncthreads();
    int t = blockIdx.x * 384 + threadIdx.x;
    if (t >= n * 12) return;
    int node = t / 12;
    int j = t - node * 12;
    const float* a = g_h1 + (size_t)node * 128;
    float s = 0.f;
#pragma unroll 8
    for (int k = 0; k < 128; k++) s += a[k] * sW[k * 12 + j];
    g_h2[t] = s;
}

// ---------------------------------------------------------------------------
// GCN message passing, layer 2 (12-dim)
// ---------------------------------------------------------------------------
__global__ void k_selfloop12(int n) {
    int idx = blockIdx.x * blockDim.x + threadIdx.x;
    if (idx >= n * 3) return;
    int node = idx / 3;
    float d = g_dinv[node]; d = d * d;
    float4 v = ((const float4*)g_h2)[idx];
    v.x *= d; v.y *= d; v.z *= d; v.w *= d;
    ((float4*)g_agg2)[idx] = v;
}
__global__ void k_edge_scatter12(const int* __restrict__ row,
                                 const int* __restrict__ col, int E) {
    int t = blockIdx.x * blockDim.x + threadIdx.x;
    int e = t / 3;
    if (e >= E) return;
    int g = t - e * 3;
    int r = row[e], c = col[e];
    float nrm = g_dinv[r] * g_dinv[c];
    float4 v = *(const float4*)(g_h2 + (size_t)r * 12 + g * 4);
    v.x *= nrm; v.y *= nrm; v.z *= nrm; v.w *= nrm;
    float* dst = g_agg2 + (size_t)c * 12 + g * 4;
    asm volatile("red.global.add.v4.f32 [%0], {%1,%2,%3,%4};"
                 :: "l"(dst), "f"(v.x), "f"(v.y), "f"(v.z), "f"(v.w) : "memory");
}

// ---------------------------------------------------------------------------
// m1 = relu(out2[N,12] @ L1[12,512] + lb1), written as bf16 hi/lo split.
// ---------------------------------------------------------------------------
__global__ void __launch_bounds__(256) k_mlp1_split(
    const float* __restrict__ L1, const float* __restrict__ lb1, int n) {
    __shared__ float sL[12 * 512];
    __shared__ float sb[512];
    __shared__ float sh[64 * 12];
    int node0 = blockIdx.x * 64;
    for (int i = threadIdx.x; i < 12 * 512; i += 256) sL[i] = L1[i];
    for (int i = threadIdx.x; i < 512; i += 256) sb[i] = lb1[i];
    for (int i = threadIdx.x; i < 64 * 12; i += 256) {
        int nn = node0 + i / 12;
        sh[i] = (nn < n) ? g_h2[(size_t)node0 * 12 + i] : 0.f;
    }
    __syncthreads();
    for (int idx = threadIdx.x; idx < 64 * 512; idx += 256) {
        int ln = idx >> 9;
        int j = idx & 511;
        int node = node0 + ln;
        float s;
        if (node < n) {
            s = sb[j];
#pragma unroll
            for (int k = 0; k < 12; k++) s += sh[ln * 12 + k] * sL[k * 512 + j];
            s = fmaxf(s, 0.f);
        } else {
            s = 0.f;
        }
        __nv_bfloat16 h = __float2bfloat16(s);
        float rem = s - __bfloat162float(h);
        size_t o = (size_t)node * 512 + j;
        g_m1h[o] = h;
        g_m1l[o] = __float2bfloat16(rem);
    }
}

// ---------------------------------------------------------------------------
// Launch
// ---------------------------------------------------------------------------
extern "C" void kernel_launch(void* const* d_in, const int* in_sizes, int n_in,
                              void* d_out, int out_size) {
    const float* x   = (const float*)d_in[0];
    const int*   ei  = (const int*)  d_in[1];
    const float* W1  = (const float*)d_in[2];
    const float* b1  = (const float*)d_in[3];
    const float* W2  = (const float*)d_in[4];
    const float* b2  = (const float*)d_in[5];
    const float* L1  = (const float*)d_in[6];
    const float* lb1 = (const float*)d_in[7];
    const float* L2  = (const float*)d_in[8];
    const float* lb2 = (const float*)d_in[9];
    const float* L3  = (const float*)d_in[10];
    const float* lb3 = (const float*)d_in[11];
    float* out = (float*)d_out;

    const int N = in_sizes[0] / 256;
    const int E = in_sizes[1] / 2;
    const int* row = ei;
    const int* col = ei + E;

    float *p_h1, *p_agg1, *p_h2, *p_agg2, *p_dinv;
    __nv_bfloat16 *p_xh, *p_xl, *p_w1th, *p_w1tl, *p_m1h, *p_m1l, *p_bth, *p_btl;
    cudaGetSymbolAddress((void**)&p_h1,   g_h1);
    cudaGetSymbolAddress((void**)&p_agg1, g_agg1);
    cudaGetSymbolAddress((void**)&p_h2,   g_h2);
    cudaGetSymbolAddress((void**)&p_agg2, g_agg2);
    cudaGetSymbolAddress((void**)&p_dinv, g_dinv);
    cudaGetSymbolAddress((void**)&p_xh,   g_xh);
    cudaGetSymbolAddress((void**)&p_xl,   g_xl);
    cudaGetSymbolAddress((void**)&p_w1th, g_w1th);
    cudaGetSymbolAddress((void**)&p_w1tl, g_w1tl);
    cudaGetSymbolAddress((void**)&p_m1h,  g_m1h);
    cudaGetSymbolAddress((void**)&p_m1l,  g_m1l);
    cudaGetSymbolAddress((void**)&p_bth,  g_bth);
    cudaGetSymbolAddress((void**)&p_btl,  g_btl);

    cudaFuncSetAttribute(k_mma<1>, cudaFuncAttributeMaxDynamicSharedMemorySize, DSM_B);
    cudaFuncSetAttribute(k_mma<2>, cudaFuncAttributeMaxDynamicSharedMemorySize, DSM_B);

    // --- degree / normalization ---
    k_deg_init <<<(N + 255) / 256, 256>>>(N);
    k_deg_edges<<<(E + 255) / 256, 256>>>(col, E);
    k_deg_rsqrt<<<(N + 255) / 256, 256>>>(N);

    // --- GCN layer 1: h1 = x @ W1 (HMMA), fused selfloop (agg1 = h1*d^2) ---
    k_split_x<<<(NMAX * 64 + 255) / 256, 256>>>(x, N);
    k_bt_prep<<<(128 * 256 + 255) / 256, 256>>>(W1, p_w1th, p_w1tl, 256, 128);
    k_mma<1><<<dim3(NMAX / 128, 1), 256, DSM_B>>>(
        p_xh, p_xl, p_w1th, p_w1tl, nullptr, p_h1, p_dinv, p_agg1,
        nullptr, nullptr, NMAX, 128, 256);
    k_edge_scatter128<<<(E * 32 + 255) / 256, 256>>>(row, col, E);
    k_bias_relu<<<(N * 128 + 255) / 256, 256>>>(p_agg1, b1, p_h1, N * 128, 128);

    // --- GCN layer 2 ---
    k_gemm_n12<<<(N * 12 + 383) / 384, 384>>>(W2, N);
    k_selfloop12<<<(N * 3 + 255) / 256, 256>>>(N);
    k_edge_scatter12<<<(E * 3 + 255) / 256, 256>>>(row, col, E);
    k_bias_relu<<<(N * 12 + 255) / 256, 256>>>(p_agg2, b2, p_h2, N * 12, 12);

    // --- MLP: m1 split, then fused GEMM(L2)+relu+GEMM(L3) -> out ---
    k_mlp1_split<<<NMAX / 64, 256>>>(L1, lb1, N);
    k_bt_prep<<<(512 * 512 + 255) / 256, 256>>>(L2, p_bth, p_btl, 512, 512);
    k_out_init<<<(N + 255) / 256, 256>>>(lb3, out, N);
    k_mma<2><<<dim3(NMAX / 128, 4), 256, DSM_B>>>(
        p_m1h, p_m1l, p_bth, p_btl, lb2, nullptr, nullptr, nullptr,
        L3, out, N, 512, 512);
}

// round 5
// speedup vs baseline: 1.9751x; 1.0714x over previous
#include <cuda_runtime.h>
#include <cuda_bf16.h>
#include <cstdint>

// ---------------------------------------------------------------------------
// Problem constants: N=50000, E=800000, F=256
// ---------------------------------------------------------------------------
#define NMAX 50176   // 50000 rounded up to multiple of 128
#define EMAX 800000

// Scratch (device globals; allocation-free kernel_launch)
__device__ float g_dinv[NMAX];
__device__ int   g_indeg[NMAX];
__device__ int   g_rowptr[NMAX + 1];
__device__ int   g_cursor[NMAX];
__device__ int   g_eidx[EMAX];
__device__ float g_h1s [(size_t)NMAX * 128];          // dinv * (x@W1)
__device__ float g_h1  [(size_t)NMAX * 128];          // out1 = relu(agg1+b1)
__device__ float g_h2s [(size_t)NMAX * 12];           // dinv * (out1@W2)
__device__ float g_h2  [(size_t)NMAX * 12];           // out2
__device__ __nv_bfloat16 g_xh [(size_t)NMAX * 256];
__device__ __nv_bfloat16 g_xl [(size_t)NMAX * 256];
__device__ __nv_bfloat16 g_w1th[128 * 256];
__device__ __nv_bfloat16 g_w1tl[128 * 256];
__device__ __nv_bfloat16 g_m1h[(size_t)NMAX * 512];
__device__ __nv_bfloat16 g_m1l[(size_t)NMAX * 512];
__device__ __nv_bfloat16 g_bth[512 * 512];
__device__ __nv_bfloat16 g_btl[512 * 512];

// ---------------------------------------------------------------------------
// PTX helpers
// ---------------------------------------------------------------------------
__device__ __forceinline__ uint32_t smem_u32(const void* p) {
    return (uint32_t)__cvta_generic_to_shared(p);
}
__device__ __forceinline__ void ldm_x4(uint32_t* r, uint32_t addr) {
    asm volatile("ldmatrix.sync.aligned.m8n8.x4.shared.b16 {%0,%1,%2,%3}, [%4];"
                 : "=r"(r[0]), "=r"(r[1]), "=r"(r[2]), "=r"(r[3]) : "r"(addr));
}
__device__ __forceinline__ void mma_bf16(float* c, const uint32_t* a,
                                         uint32_t b0, uint32_t b1) {
    asm volatile(
        "mma.sync.aligned.m16n8k16.row.col.f32.bf16.bf16.f32 "
        "{%0,%1,%2,%3}, {%4,%5,%6,%7}, {%8,%9}, {%0,%1,%2,%3};"
        : "+f"(c[0]), "+f"(c[1]), "+f"(c[2]), "+f"(c[3])
        : "r"(a[0]), "r"(a[1]), "r"(a[2]), "r"(a[3]), "r"(b0), "r"(b1));
}
#define CP_ASYNC16(dst, src) \
    asm volatile("cp.async.cg.shared.global [%0], [%1], 16;" :: "r"(dst), "l"(src))
#define CP_COMMIT() asm volatile("cp.async.commit_group;" ::: "memory")
#define CP_WAIT1()  asm volatile("cp.async.wait_group 1;" ::: "memory")

__device__ __forceinline__ uint32_t pk_bf2(__nv_bfloat16 a, __nv_bfloat16 b) {
    __nv_bfloat162 t(a, b);
    return *reinterpret_cast<uint32_t*>(&t);
}

// ---------------------------------------------------------------------------
// Degree / dinv / CSR build
// ---------------------------------------------------------------------------
__global__ void k_ideg_init() {
    int i = blockIdx.x * blockDim.x + threadIdx.x;
    if (i < NMAX) g_indeg[i] = 0;
}
__global__ void k_ideg_edges(const int* __restrict__ col, int E) {
    int e = blockIdx.x * blockDim.x + threadIdx.x;
    if (e < E) atomicAdd(&g_indeg[col[e]], 1);
}
__global__ void k_dinv_calc() {
    int i = blockIdx.x * blockDim.x + threadIdx.x;
    if (i < NMAX) g_dinv[i] = rsqrtf((float)(g_indeg[i] + 1));
}
// Single-block exclusive scan of g_indeg[0..n) -> g_rowptr (warp-scan based)
__global__ void __launch_bounds__(1024) k_scan(int n) {
    __shared__ int wsum[32];
    __shared__ int carry;
    const int tid = threadIdx.x, lane = tid & 31, wid = tid >> 5;
    if (tid == 0) carry = 0;
    __syncthreads();
    for (int base = 0; base < n; base += 1024) {
        int i = base + tid;
        int v = (i < n) ? g_indeg[i] : 0;
        int s = v;
#pragma unroll
        for (int o = 1; o < 32; o <<= 1) {
            int t = __shfl_up_sync(0xffffffffu, s, o);
            if (lane >= o) s += t;
        }
        if (lane == 31) wsum[wid] = s;
        __syncthreads();
        if (wid == 0) {
            int w = wsum[lane];
#pragma unroll
            for (int o = 1; o < 32; o <<= 1) {
                int t = __shfl_up_sync(0xffffffffu, w, o);
                if (lane >= o) w += t;
            }
            wsum[lane] = w;
        }
        __syncthreads();
        int excl = carry + s - v + (wid ? wsum[wid - 1] : 0);
        if (i < n) { g_rowptr[i] = excl; g_cursor[i] = excl; }
        int tot = wsum[31];
        __syncthreads();
        if (tid == 0) carry += tot;
        __syncthreads();
    }
    if (tid == 0) g_rowptr[n] = carry;
}
__global__ void k_fill(const int* __restrict__ row,
                       const int* __restrict__ col, int E) {
    int e = blockIdx.x * blockDim.x + threadIdx.x;
    if (e >= E) return;
    int p = atomicAdd(&g_cursor[col[e]], 1);
    g_eidx[p] = row[e];
}

// ---------------------------------------------------------------------------
// Splits / transposed-weight prep
// ---------------------------------------------------------------------------
__global__ void k_split_x(const float* __restrict__ x, int n) {
    int i = blockIdx.x * blockDim.x + threadIdx.x;   // over NMAX*64 float4s
    if (i >= NMAX * 64) return;
    int node = i >> 6;
    float4 v = (node < n) ? ((const float4*)x)[i]
                          : make_float4(0.f, 0.f, 0.f, 0.f);
    __nv_bfloat16 h0 = __float2bfloat16(v.x), h1 = __float2bfloat16(v.y);
    __nv_bfloat16 h2 = __float2bfloat16(v.z), h3 = __float2bfloat16(v.w);
    ((uint2*)g_xh)[i] = make_uint2(pk_bf2(h0, h1), pk_bf2(h2, h3));
    float l0 = v.x - __bfloat162float(h0), l1 = v.y - __bfloat162float(h1);
    float l2 = v.z - __bfloat162float(h2), l3 = v.w - __bfloat162float(h3);
    ((uint2*)g_xl)[i] = make_uint2(
        pk_bf2(__float2bfloat16(l0), __float2bfloat16(l1)),
        pk_bf2(__float2bfloat16(l2), __float2bfloat16(l3)));
}
__global__ void k_bt_prep(const float* __restrict__ W,
                          __nv_bfloat16* __restrict__ th,
                          __nv_bfloat16* __restrict__ tl, int K, int N) {
    int i = blockIdx.x * blockDim.x + threadIdx.x;
    if (i >= N * K) return;
    int n = i / K, k = i - n * K;
    float v = W[(size_t)k * N + n];
    __nv_bfloat16 h = __float2bfloat16(v);
    th[i] = h;
    tl[i] = __float2bfloat16(v - __bfloat162float(h));
}
__global__ void k_out_init(const float* __restrict__ lb3,
                           float* __restrict__ out, int n) {
    int i = blockIdx.x * blockDim.x + threadIdx.x;
    if (i < n) ((float2*)out)[i] = make_float2(lb3[0], lb3[1]);
}

// ---------------------------------------------------------------------------
// bf16 split-MMA GEMM, 2-stage cp.async pipeline (3-term split).
// MODE 1: C[m] = dinv[m] * acc                (layer-1: h1s)
// MODE 2: relu(acc+bias) @ L3 -> RED into out (fused final layer)
// ---------------------------------------------------------------------------
#define SMP 40
#define MAT_B (128 * SMP * 2)
#define BUF_B (4 * MAT_B)
#define DSM_B (2 * BUF_B + 1024)

template <int MODE>
__global__ void __launch_bounds__(256) k_mma(
    const __nv_bfloat16* __restrict__ Ah, const __nv_bfloat16* __restrict__ Al,
    const __nv_bfloat16* __restrict__ BTh, const __nv_bfloat16* __restrict__ BTl,
    const float* __restrict__ bias, float* __restrict__ C,
    const float* __restrict__ dinv,
    const float* __restrict__ L3, float* __restrict__ outp,
    int Mreal, int N, int K)
{
    extern __shared__ char dsm[];
    const uint32_t sb = smem_u32(dsm);
    float* sL3 = (float*)(dsm + 2 * BUF_B);

    const int tid = threadIdx.x;
    const int lane = tid & 31;
    const int wid = tid >> 5;
    const int wm = (wid & 3) * 32;
    const int wn = (wid >> 2) * 64;
    const int m0 = blockIdx.x * 128;
    const int n0 = blockIdx.y * 128;

    if (MODE == 2) {
        if (tid < 128) ((float2*)sL3)[tid] = ((const float2*)L3)[n0 + tid];
    }

    float acc[2][8][4];
#pragma unroll
    for (int i = 0; i < 2; i++)
#pragma unroll
        for (int j = 0; j < 8; j++)
#pragma unroll
            for (int t = 0; t < 4; t++) acc[i][j][t] = 0.f;

    const int a_lr = lane & 15, a_lc = (lane >> 4) * 8;
    const int b_lr = (lane & 7) + ((lane >> 4) << 3);
    const int b_lc = ((lane >> 3) & 1) * 8;
    const int ntiles = K >> 5;

    auto issue = [&](int kt, int buf) {
#pragma unroll
        for (int j = 0; j < 2; j++) {
            int s = tid + j * 256;
            int row = s >> 2, q = s & 3;
            uint32_t so = sb + buf * BUF_B + (uint32_t)(row * SMP + q * 8) * 2;
            size_t ga = (size_t)(m0 + row) * K + kt * 32 + q * 8;
            size_t gb = (size_t)(n0 + row) * K + kt * 32 + q * 8;
            CP_ASYNC16(so,             Ah + ga);
            CP_ASYNC16(so + MAT_B,     Al + ga);
            CP_ASYNC16(so + 2 * MAT_B, BTh + gb);
            CP_ASYNC16(so + 3 * MAT_B, BTl + gb);
        }
    };

    issue(0, 0);
    CP_COMMIT();

    for (int kt = 0; kt < ntiles; kt++) {
        const int cur = kt & 1;
        if (kt + 1 < ntiles) issue(kt + 1, cur ^ 1);
        CP_COMMIT();
        CP_WAIT1();
        __syncthreads();

        const uint32_t bA = sb + cur * BUF_B;
#pragma unroll
        for (int ks = 0; ks < 2; ks++) {
            uint32_t ah[2][4], al[2][4], bh[4][4], bl[4][4];
#pragma unroll
            for (int mt = 0; mt < 2; mt++) {
                uint32_t off = (uint32_t)((wm + mt * 16 + a_lr) * SMP
                                          + ks * 16 + a_lc) * 2;
                ldm_x4(ah[mt], bA + off);
                ldm_x4(al[mt], bA + MAT_B + off);
            }
#pragma unroll
            for (int p = 0; p < 4; p++) {
                uint32_t off = (uint32_t)((wn + p * 16 + b_lr) * SMP
                                          + ks * 16 + b_lc) * 2;
                ldm_x4(bh[p], bA + 2 * MAT_B + off);
                ldm_x4(bl[p], bA + 3 * MAT_B + off);
            }
#pragma unroll
            for (int mt = 0; mt < 2; mt++)
#pragma unroll
                for (int nt = 0; nt < 8; nt++) {
                    int p = nt >> 1, h = (nt & 1) * 2;
                    mma_bf16(acc[mt][nt], ah[mt], bh[p][h], bh[p][h + 1]);
                    mma_bf16(acc[mt][nt], ah[mt], bl[p][h], bl[p][h + 1]);
                    mma_bf16(acc[mt][nt], al[mt], bh[p][h], bh[p][h + 1]);
                }
        }
        __syncthreads();
    }

    // ---------------- epilogue ----------------
    if (MODE == 2) {
        float pr[4][2];
#pragma unroll
        for (int i = 0; i < 4; i++) { pr[i][0] = 0.f; pr[i][1] = 0.f; }
#pragma unroll
        for (int mt = 0; mt < 2; mt++)
#pragma unroll
            for (int r = 0; r < 2; r++) {
                int idx = mt * 2 + r;
#pragma unroll
                for (int nt = 0; nt < 8; nt++) {
                    int n = wn + nt * 8 + (lane & 3) * 2;
                    float v0 = fmaxf(acc[mt][nt][r * 2 + 0] + bias[n0 + n], 0.f);
                    float v1 = fmaxf(acc[mt][nt][r * 2 + 1] + bias[n0 + n + 1], 0.f);
                    pr[idx][0] += v0 * sL3[2 * n + 0] + v1 * sL3[2 * (n + 1) + 0];
                    pr[idx][1] += v0 * sL3[2 * n + 1] + v1 * sL3[2 * (n + 1) + 1];
                }
            }
#pragma unroll
        for (int i = 0; i < 4; i++) {
#pragma unroll
            for (int o = 1; o < 4; o <<= 1) {
                pr[i][0] += __shfl_xor_sync(0xffffffffu, pr[i][0], o);
                pr[i][1] += __shfl_xor_sync(0xffffffffu, pr[i][1], o);
            }
        }
        if ((lane & 3) == 0) {
#pragma unroll
            for (int mt = 0; mt < 2; mt++)
#pragma unroll
                for (int r = 0; r < 2; r++) {
                    int m = m0 + wm + mt * 16 + (lane >> 2) + r * 8;
                    if (m < Mreal) {
                        float* dst = outp + (size_t)m * 2;
                        asm volatile("red.global.add.v2.f32 [%0], {%1,%2};"
                                     :: "l"(dst), "f"(pr[mt * 2 + r][0]),
                                        "f"(pr[mt * 2 + r][1]) : "memory");
                    }
                }
        }
        return;
    }

#pragma unroll
    for (int mt = 0; mt < 2; mt++) {
#pragma unroll
        for (int r = 0; r < 2; r++) {
            int m = m0 + wm + mt * 16 + (lane >> 2) + r * 8;
            float d = dinv[m];
#pragma unroll
            for (int nt = 0; nt < 8; nt++) {
                int n = n0 + wn + nt * 8 + (lane & 3) * 2;
                *(float2*)(C + (size_t)m * N + n)
                    = make_float2(acc[mt][nt][r * 2 + 0] * d,
                                  acc[mt][nt][r * 2 + 1] * d);
            }
        }
    }
}

// ---------------------------------------------------------------------------
// CSR gather, layer 1: out1[c] = relu(dinv[c]*(h1s[c] + sum_in h1s[r]) + b1)
// One warp per node; lane holds float4 (128 dims / 32 lanes).
// ---------------------------------------------------------------------------
__global__ void k_gather128(const float* __restrict__ b1, int n) {
    int w = (blockIdx.x * blockDim.x + threadIdx.x) >> 5;
    int lane = threadIdx.x & 31;
    if (w >= n) return;
    int s = g_rowptr[w], e = g_rowptr[w + 1];
    const float4* base = (const float4*)g_h1s;
    float4 acc = base[(size_t)w * 32 + lane];     // self term
    int i = s;
    for (; i + 1 < e; i += 2) {
        int r0 = __ldg(&g_eidx[i]);
        int r1 = __ldg(&g_eidx[i + 1]);
        float4 v0 = base[(size_t)r0 * 32 + lane];
        float4 v1 = base[(size_t)r1 * 32 + lane];
        acc.x += v0.x + v1.x; acc.y += v0.y + v1.y;
        acc.z += v0.z + v1.z; acc.w += v0.w + v1.w;
    }
    if (i < e) {
        int r = __ldg(&g_eidx[i]);
        float4 v = base[(size_t)r * 32 + lane];
        acc.x += v.x; acc.y += v.y; acc.z += v.z; acc.w += v.w;
    }
    float d = g_dinv[w];
    float4 bb = ((const float4*)b1)[lane];
    float4 o;
    o.x = fmaxf(acc.x * d + bb.x, 0.f);
    o.y = fmaxf(acc.y * d + bb.y, 0.f);
    o.z = fmaxf(acc.z * d + bb.z, 0.f);
    o.w = fmaxf(acc.w * d + bb.w, 0.f);
    ((float4*)g_h1)[(size_t)w * 32 + lane] = o;
}

// ---------------------------------------------------------------------------
// h2s[N,12] = dinv * (out1[N,128] @ W2[128,12])
// ---------------------------------------------------------------------------
__global__ void k_gemm_n12(const float* __restrict__ W2, int n) {
    __shared__ float sW[128 * 12];
    for (int i = threadIdx.x; i < 128 * 12; i += 384) sW[i] = W2[i];
    __syncthreads();
    int t = blockIdx.x * 384 + threadIdx.x;
    if (t >= n * 12) return;
    int node = t / 12;
    int j = t - node * 12;
    const float* a = g_h1 + (size_t)node * 128;
    float s = 0.f;
#pragma unroll 8
    for (int k = 0; k < 128; k++) s += a[k] * sW[k * 12 + j];
    g_h2s[t] = s * g_dinv[node];
}

// ---------------------------------------------------------------------------
// CSR gather, layer 2 (12-dim): lanes 0-11 of a warp per node
// ---------------------------------------------------------------------------
__global__ void k_gather12(const float* __restrict__ b2, int n) {
    int w = (blockIdx.x * blockDim.x + threadIdx.x) >> 5;
    int lane = threadIdx.x & 31;
    if (w >= n) return;
    int s = g_rowptr[w], e = g_rowptr[w + 1];
    float acc = (lane < 12) ? g_h2s[(size_t)w * 12 + lane] : 0.f;
    for (int i = s; i < e; i++) {
        int r = __ldg(&g_eidx[i]);
        if (lane < 12) acc += g_h2s[(size_t)r * 12 + lane];
    }
    if (lane < 12) {
        float d = g_dinv[w];
        g_h2[(size_t)w * 12 + lane] = fmaxf(acc * d + b2[lane], 0.f);
    }
}

// ---------------------------------------------------------------------------
// m1 = relu(out2[N,12] @ L1[12,512] + lb1) -> bf16 hi/lo split
// ---------------------------------------------------------------------------
__global__ void __launch_bounds__(256) k_mlp1_split(
    const float* __restrict__ L1, const float* __restrict__ lb1, int n) {
    __shared__ float sL[12 * 512];
    __shared__ float sb[512];
    __shared__ float sh[64 * 12];
    int node0 = blockIdx.x * 64;
    for (int i = threadIdx.x; i < 12 * 512; i += 256) sL[i] = L1[i];
    for (int i = threadIdx.x; i < 512; i += 256) sb[i] = lb1[i];
    for (int i = threadIdx.x; i < 64 * 12; i += 256) {
        int nn = node0 + i / 12;
        sh[i] = (nn < n) ? g_h2[(size_t)node0 * 12 + i] : 0.f;
    }
    __syncthreads();
    for (int idx = threadIdx.x; idx < 64 * 512; idx += 256) {
        int ln = idx >> 9;
        int j = idx & 511;
        int node = node0 + ln;
        float s;
        if (node < n) {
            s = sb[j];
#pragma unroll
            for (int k = 0; k < 12; k++) s += sh[ln * 12 + k] * sL[k * 512 + j];
            s = fmaxf(s, 0.f);
        } else {
            s = 0.f;
        }
        __nv_bfloat16 h = __float2bfloat16(s);
        float rem = s - __bfloat162float(h);
        size_t o = (size_t)node * 512 + j;
        g_m1h[o] = h;
        g_m1l[o] = __float2bfloat16(rem);
    }
}

// ---------------------------------------------------------------------------
// Launch
// ---------------------------------------------------------------------------
extern "C" void kernel_launch(void* const* d_in, const int* in_sizes, int n_in,
                              void* d_out, int out_size) {
    const float* x   = (const float*)d_in[0];
    const int*   ei  = (const int*)  d_in[1];
    const float* W1  = (const float*)d_in[2];
    const float* b1  = (const float*)d_in[3];
    const float* W2  = (const float*)d_in[4];
    const float* b2  = (const float*)d_in[5];
    const float* L1  = (const float*)d_in[6];
    const float* lb1 = (const float*)d_in[7];
    const float* L2  = (const float*)d_in[8];
    const float* lb2 = (const float*)d_in[9];
    const float* L3  = (const float*)d_in[10];
    const float* lb3 = (const float*)d_in[11];
    float* out = (float*)d_out;

    const int N = in_sizes[0] / 256;
    const int E = in_sizes[1] / 2;
    const int* row = ei;
    const int* col = ei + E;

    float *p_h1s, *p_dinv;
    __nv_bfloat16 *p_xh, *p_xl, *p_w1th, *p_w1tl, *p_m1h, *p_m1l, *p_bth, *p_btl;
    cudaGetSymbolAddress((void**)&p_h1s,  g_h1s);
    cudaGetSymbolAddress((void**)&p_dinv, g_dinv);
    cudaGetSymbolAddress((void**)&p_xh,   g_xh);
    cudaGetSymbolAddress((void**)&p_xl,   g_xl);
    cudaGetSymbolAddress((void**)&p_w1th, g_w1th);
    cudaGetSymbolAddress((void**)&p_w1tl, g_w1tl);
    cudaGetSymbolAddress((void**)&p_m1h,  g_m1h);
    cudaGetSymbolAddress((void**)&p_m1l,  g_m1l);
    cudaGetSymbolAddress((void**)&p_bth,  g_bth);
    cudaGetSymbolAddress((void**)&p_btl,  g_btl);

    cudaFuncSetAttribute(k_mma<1>, cudaFuncAttributeMaxDynamicSharedMemorySize, DSM_B);
    cudaFuncSetAttribute(k_mma<2>, cudaFuncAttributeMaxDynamicSharedMemorySize, DSM_B);

    // --- degrees, dinv, CSR ---
    k_ideg_init <<<(NMAX + 255) / 256, 256>>>();
    k_ideg_edges<<<(E + 255) / 256, 256>>>(col, E);
    k_dinv_calc <<<(NMAX + 255) / 256, 256>>>();
    k_scan      <<<1, 1024>>>(N);
    k_fill      <<<(E + 255) / 256, 256>>>(row, col, E);

    // --- GCN layer 1: h1s = dinv*(x@W1); CSR gather -> out1 ---
    k_split_x<<<(NMAX * 64 + 255) / 256, 256>>>(x, N);
    k_bt_prep<<<(128 * 256 + 255) / 256, 256>>>(W1, p_w1th, p_w1tl, 256, 128);
    k_mma<1><<<dim3(NMAX / 128, 1), 256, DSM_B>>>(
        p_xh, p_xl, p_w1th, p_w1tl, nullptr, p_h1s, p_dinv,
        nullptr, nullptr, NMAX, 128, 256);
    k_gather128<<<(N * 32 + 255) / 256, 256>>>(b1, N);

    // --- GCN layer 2 ---
    k_gemm_n12<<<(N * 12 + 383) / 384, 384>>>(W2, N);
    k_gather12<<<(N * 32 + 255) / 256, 256>>>(b2, N);

    // --- MLP: m1 split, fused GEMM(L2)+relu+GEMM(L3) -> out ---
    k_mlp1_split<<<NMAX / 64, 256>>>(L1, lb1, N);
    k_bt_prep<<<(512 * 512 + 255) / 256, 256>>>(L2, p_bth, p_btl, 512, 512);
    k_out_init<<<(N + 255) / 256, 256>>>(lb3, out, N);
    k_mma<2><<<dim3(NMAX / 128, 4), 256, DSM_B>>>(
        p_m1h, p_m1l, p_bth, p_btl, lb2, nullptr, nullptr,
        L3, out, N, 512, 512);
}